// round 16
// baseline (speedup 1.0000x reference)
#include <cuda_runtime.h>
#include <cuda_bf16.h>
#include <math.h>
#include <stdint.h>

#define BB 16384
#define XD 2000
#define HD 100
#define ZD 20
#define KTOT (2*XD)      // 4000
#define LN_EPS 1e-5f

// ---------------- scratch (static device globals; no allocations) -------------
__device__ float g_h1 [(size_t)BB*HD];
__device__ float g_h1g[(size_t)BB*HD];
__device__ float g_th [(size_t)BB*HD];
__device__ float g_ld [(size_t)BB*XD];
__device__ float g_tld[(size_t)BB*XD];
__device__ float g_beta [XD];
__device__ float g_gamma[XD];
// W1 pre-transposed bf16 split: [n(128, rows >=100 zero)][kword(2000)]
__device__ uint32_t g_w1hi[128 * 2000];
__device__ uint32_t g_w1lo[128 * 2000];
// W2 pre-transposed bf16 split: [n(2048, cols >=2000 zero)][kword(56, >=50 zero)]
__device__ uint32_t g_w2hi[2048 * 56];
__device__ uint32_t g_w2lo[2048 * 56];

// ---------------- helpers -----------------------------------------------------
__device__ __forceinline__ float softplusf(float x) {
    return fmaxf(x, 0.f) + log1pf(expf(-fabsf(x)));
}
__device__ __forceinline__ float softplus_fast(float x) {
    return fmaxf(x, 0.f) + __logf(1.f + __expf(-fabsf(x)));
}
__device__ __forceinline__ float sigmoid_fast(float x) {
    return __fdividef(1.f, 1.f + __expf(-x));
}
__device__ __forceinline__ float geluf(float x) {
    return 0.5f * x * (1.f + erff(x * 0.70710678118654752f));
}
__device__ __forceinline__ float wsum(float v) {
#pragma unroll
    for (int o = 16; o; o >>= 1) v += __shfl_xor_sync(0xffffffffu, v, o);
    return v;
}

// split fp32 pair -> bf16x2 hi + bf16x2 lo (lo = rounded residual); low half = .x
__device__ __forceinline__ void bfsplit2(float2 v, uint32_t& hi, uint32_t& lo) {
    asm("cvt.rn.bf16x2.f32 %0, %1, %2;" : "=r"(hi) : "f"(v.y), "f"(v.x));
    float hx = __uint_as_float(hi << 16);
    float hy = __uint_as_float(hi & 0xFFFF0000u);
    float rx = v.x - hx;
    float ry = v.y - hy;
    asm("cvt.rn.bf16x2.f32 %0, %1, %2;" : "=r"(lo) : "f"(ry), "f"(rx));
}

// m16n8k16 bf16 MMA, fp32 accumulate (legacy HMMA path, valid at compute_103)
#define MMA_BF16(d, a0, a1, a2, a3, b0, b1) \
    asm volatile("mma.sync.aligned.m16n8k16.row.col.f32.bf16.bf16.f32 " \
        "{%0,%1,%2,%3}, {%4,%5,%6,%7}, {%8,%9}, {%0,%1,%2,%3};" \
        : "+f"((d)[0]), "+f"((d)[1]), "+f"((d)[2]), "+f"((d)[3]) \
        : "r"(a0), "r"(a1), "r"(a2), "r"(a3), "r"(b0), "r"(b1))

// ---------------- k0: beta/gamma precompute ----------------------------------
__global__ void k0_rates(const float* __restrict__ lb, const float* __restrict__ lg) {
    int i = blockIdx.x * blockDim.x + threadIdx.x;
    if (i < XD) {
        g_beta[i]  = softplusf(lb[i]);   // * DT (=1)
        g_gamma[i] = softplusf(lg[i]);
    }
}

// ---------------- k0b: W1 -> transposed bf16 split (128 rows, zero pad) -------
__global__ void k0b_w1split(const float* __restrict__ w1) {
    int idx = blockIdx.x * 256 + threadIdx.x;
    if (idx >= 128 * 2000) return;
    int n = idx / 2000, kw = idx - n * 2000;
    float2 v = make_float2(0.f, 0.f);
    if (n < HD) {
        v.x = w1[(size_t)(2 * kw) * HD + n];
        v.y = w1[(size_t)(2 * kw + 1) * HD + n];
    }
    uint32_t hi, lo;
    bfsplit2(v, hi, lo);
    g_w1hi[idx] = hi;
    g_w1lo[idx] = lo;
}

// ---------------- k0c: W2 -> transposed bf16 split (2048 x 56, zero pad) ------
__global__ void k0c_w2split(const float* __restrict__ w2) {
    int idx = blockIdx.x * 256 + threadIdx.x;
    if (idx >= 2048 * 56) return;
    int n = idx / 56, w = idx - n * 56;
    float2 v = make_float2(0.f, 0.f);
    if (n < XD && w < 50) {
        v.x = w2[(size_t)(2 * w) * XD + n];
        v.y = w2[(size_t)(2 * w + 1) * XD + n];
    }
    uint32_t hi, lo;
    bfsplit2(v, hi, lo);
    g_w2hi[idx] = hi;
    g_w2lo[idx] = lo;
}

// ---------------- k1: double-buffered mma.sync bf16-split, M64 x N112 ---------
// (unchanged from R15 — measured at the legacy-HMMA pipe ceiling, 202 us)
#define K1RS 36
#define K1BUF 12672                 // words per buffer
#define K1_AHo 0
#define K1_ALo 2304
#define K1_BHo 4608
#define K1_BLo 8640
#define K1_SMEM_BYTES (2 * K1BUF * 4)   // 101376

__global__ void __launch_bounds__(256, 1) k1_mma(
    const float* __restrict__ s, const float* __restrict__ u,
    const float* __restrict__ b1)
{
    extern __shared__ uint32_t smu[];
    int tid = threadIdx.x, wid = tid >> 5, lane = tid & 31;
    int m0 = blockIdx.x * 64;
    int g = lane >> 2, tg = lane & 3;
    int mwarp = wid & 3, nh = wid >> 2;

    int aRow[2], aW4[2];
#pragma unroll
    for (int t = 0; t < 2; t++) {
        int lin = tid + t * 256;
        aRow[t] = lin >> 3;
        aW4 [t] = (lin & 7) * 4;
    }
    int bN[4], bG4[4];
#pragma unroll
    for (int i = 0; i < 4; i++) {
        int lin = tid + i * 256;
        bN[i]  = lin >> 3;
        bG4[i] = (lin & 7) * 4;
    }
    bool b3v = (tid < 128);

    float4 aP0[2], aP1[2];
    uint4 bPH[4], bPL[4];

#define K1_LDG(kw0_) do {                                                       \
        _Pragma("unroll")                                                       \
        for (int t_ = 0; t_ < 2; t_++) {                                        \
            int kw_ = (kw0_) + aW4[t_];                                         \
            aP0[t_] = make_float4(0.f,0.f,0.f,0.f); aP1[t_] = aP0[t_];          \
            if (kw_ < 1000) {                                                   \
                const float* p_ = &s[(size_t)(m0 + aRow[t_]) * XD + 2 * kw_];   \
                aP0[t_] = *(const float4*)p_; aP1[t_] = *(const float4*)(p_+4); \
            } else if (kw_ < 2000) {                                            \
                const float* p_ = &u[(size_t)(m0 + aRow[t_]) * XD + 2*kw_ - XD];\
                aP0[t_] = *(const float4*)p_; aP1[t_] = *(const float4*)(p_+4); \
            }                                                                   \
        }                                                                       \
        _Pragma("unroll")                                                       \
        for (int i_ = 0; i_ < 4; i_++) {                                        \
            int kb_ = (kw0_) + bG4[i_];                                         \
            bPH[i_] = make_uint4(0u,0u,0u,0u); bPL[i_] = bPH[i_];               \
            if ((i_ < 3 || b3v) && kb_ < 2000) {                                \
                bPH[i_] = *(const uint4*)&g_w1hi[bN[i_] * 2000 + kb_];          \
                bPL[i_] = *(const uint4*)&g_w1lo[bN[i_] * 2000 + kb_];          \
            }                                                                   \
        }                                                                       \
    } while (0)

#define K1_STS(b_) do {                                                         \
        _Pragma("unroll")                                                       \
        for (int t_ = 0; t_ < 2; t_++) {                                        \
            uint32_t h_[4], l_[4];                                              \
            bfsplit2(make_float2(aP0[t_].x, aP0[t_].y), h_[0], l_[0]);          \
            bfsplit2(make_float2(aP0[t_].z, aP0[t_].w), h_[1], l_[1]);          \
            bfsplit2(make_float2(aP1[t_].x, aP1[t_].y), h_[2], l_[2]);          \
            bfsplit2(make_float2(aP1[t_].z, aP1[t_].w), h_[3], l_[3]);          \
            *(uint4*)&smu[(b_)*K1BUF + K1_AHo + aRow[t_]*K1RS + aW4[t_]] =      \
                make_uint4(h_[0], h_[1], h_[2], h_[3]);                         \
            *(uint4*)&smu[(b_)*K1BUF + K1_ALo + aRow[t_]*K1RS + aW4[t_]] =      \
                make_uint4(l_[0], l_[1], l_[2], l_[3]);                         \
        }                                                                       \
        _Pragma("unroll")                                                       \
        for (int i_ = 0; i_ < 4; i_++) {                                        \
            if (i_ < 3 || b3v) {                                                \
                *(uint4*)&smu[(b_)*K1BUF + K1_BHo + bN[i_]*K1RS + bG4[i_]] = bPH[i_];\
                *(uint4*)&smu[(b_)*K1BUF + K1_BLo + bN[i_]*K1RS + bG4[i_]] = bPL[i_];\
            }                                                                   \
        }                                                                       \
    } while (0)

    float dM[7][4], dL[7][4];
#pragma unroll
    for (int j = 0; j < 7; j++)
#pragma unroll
        for (int e = 0; e < 4; e++) { dM[j][e] = 0.f; dL[j][e] = 0.f; }

    K1_LDG(0);
    K1_STS(0);
    __syncthreads();

    int b = 0;
    for (int c = 0; c < 63; c++) {
        if (c < 62) K1_LDG((c + 1) * 32);

        int abH = b * K1BUF + K1_AHo + (mwarp * 16 + g) * K1RS;
        int abL = abH + (K1_ALo - K1_AHo);
#pragma unroll
        for (int ks = 0; ks < 4; ks++) {
            int kw = ks * 8 + tg;
            uint32_t ah0 = smu[abH + kw];
            uint32_t ah1 = smu[abH + 8 * K1RS + kw];
            uint32_t ah2 = smu[abH + kw + 4];
            uint32_t ah3 = smu[abH + 8 * K1RS + kw + 4];
            uint32_t al0 = smu[abL + kw];
            uint32_t al1 = smu[abL + 8 * K1RS + kw];
            uint32_t al2 = smu[abL + kw + 4];
            uint32_t al3 = smu[abL + 8 * K1RS + kw + 4];
            uint32_t bh0r[7], bh1r[7], bl0r[7], bl1r[7];
#pragma unroll
            for (int j = 0; j < 7; j++) {
                int bb = b * K1BUF + K1_BHo + (nh * 56 + 8 * j + g) * K1RS + kw;
                bh0r[j] = smu[bb];
                bh1r[j] = smu[bb + 4];
                bl0r[j] = smu[bb + (K1_BLo - K1_BHo)];
                bl1r[j] = smu[bb + (K1_BLo - K1_BHo) + 4];
            }
#pragma unroll
            for (int j = 0; j < 7; j++)
                MMA_BF16(dM[j], ah0, ah1, ah2, ah3, bh0r[j], bh1r[j]);
#pragma unroll
            for (int j = 0; j < 7; j++)
                MMA_BF16(dM[j], ah0, ah1, ah2, ah3, bl0r[j], bl1r[j]);
#pragma unroll
            for (int j = 0; j < 7; j++)
                MMA_BF16(dL[j], al0, al1, al2, al3, bh0r[j], bh1r[j]);
        }

        if (c < 62) K1_STS(b ^ 1);
        __syncthreads();
        b ^= 1;
    }

    // ---- epilogue: LN over N per row (2 halves joined via smem) + GELU ----
    float* red = (float*)smu;    // [64 rows][2 halves][2 {sum,sq}]
    int lr0 = mwarp * 16 + g;
    int lr1 = lr0 + 8;

    float s0 = 0.f, q0 = 0.f, s1 = 0.f, q1 = 0.f;
#pragma unroll
    for (int j = 0; j < 7; j++) {
        int col = nh * 56 + 8 * j + 2 * tg;
        if (col < HD) {
            float bx = b1[col], by = b1[col + 1];
            float x0 = dM[j][0] + dL[j][0] + bx;
            float x1 = dM[j][1] + dL[j][1] + by;
            float x2 = dM[j][2] + dL[j][2] + bx;
            float x3 = dM[j][3] + dL[j][3] + by;
            s0 += x0 + x1; q0 += x0 * x0 + x1 * x1;
            s1 += x2 + x3; q1 += x2 * x2 + x3 * x3;
        }
    }
#pragma unroll
    for (int o = 1; o <= 2; o <<= 1) {
        s0 += __shfl_xor_sync(0xffffffffu, s0, o);
        q0 += __shfl_xor_sync(0xffffffffu, q0, o);
        s1 += __shfl_xor_sync(0xffffffffu, s1, o);
        q1 += __shfl_xor_sync(0xffffffffu, q1, o);
    }
    if (tg == 0) {
        red[(lr0 * 2 + nh) * 2 + 0] = s0;
        red[(lr0 * 2 + nh) * 2 + 1] = q0;
        red[(lr1 * 2 + nh) * 2 + 0] = s1;
        red[(lr1 * 2 + nh) * 2 + 1] = q1;
    }
    __syncthreads();

    float sum0 = red[(lr0*2+0)*2] + red[(lr0*2+1)*2];
    float sq0  = red[(lr0*2+0)*2+1] + red[(lr0*2+1)*2+1];
    float sum1 = red[(lr1*2+0)*2] + red[(lr1*2+1)*2];
    float sq1  = red[(lr1*2+0)*2+1] + red[(lr1*2+1)*2+1];
    float mean0 = sum0 * (1.f / HD);
    float mean1 = sum1 * (1.f / HD);
    float rs0 = rsqrtf(sq0 * (1.f / HD) - mean0 * mean0 + LN_EPS);
    float rs1 = rsqrtf(sq1 * (1.f / HD) - mean1 * mean1 + LN_EPS);

    int r0 = m0 + lr0, r1 = m0 + lr1;
#pragma unroll
    for (int j = 0; j < 7; j++) {
        int col = nh * 56 + 8 * j + 2 * tg;
        if (col < HD) {
            float bx = b1[col], by = b1[col + 1];
            float2 o0, o1;
            o0.x = geluf((dM[j][0] + dL[j][0] + bx - mean0) * rs0);
            o0.y = geluf((dM[j][1] + dL[j][1] + by - mean0) * rs0);
            o1.x = geluf((dM[j][2] + dL[j][2] + bx - mean1) * rs1);
            o1.y = geluf((dM[j][3] + dL[j][3] + by - mean1) * rs1);
            *(float2*)&g_h1[(size_t)r0 * HD + col] = o0;
            *(float2*)&g_h1[(size_t)r1 * HD + col] = o1;
        }
    }
}

// ---------------- k2: everything small, one warp per row (smem w2) ------------
#define K2_SMEM_FLOATS (22380 + 8*264)
__global__ void __launch_bounds__(256) k2_mid(
    const float* __restrict__ eps_z, const float* __restrict__ eps_d,
    const float* __restrict__ w2, const float* __restrict__ b2,
    const float* __restrict__ wmu, const float* __restrict__ bmu,
    const float* __restrict__ wlv, const float* __restrict__ blv,
    const float* __restrict__ edw1, const float* __restrict__ edb1,
    const float* __restrict__ edwmu, const float* __restrict__ edbmu,
    const float* __restrict__ edwlv, const float* __restrict__ edblv,
    const float* __restrict__ dzw1, const float* __restrict__ dzb1,
    float* __restrict__ o_z, float* __restrict__ o_dz,
    float* __restrict__ o_muz, float* __restrict__ o_scz,
    float* __restrict__ o_mud, float* __restrict__ o_scd)
{
    extern __shared__ float sm2[];
    float* sw2    = sm2;              // 10000
    float* swmu   = sw2 + 10000;      // 2000
    float* swlv   = swmu + 2000;      // 2000
    float* sb2    = swlv + 2000;      // 100
    float* sbmu   = sb2 + 100;        // 20
    float* sblv   = sbmu + 20;        // 20
    float* sedw1  = sblv + 20;        // 2000
    float* sedb1  = sedw1 + 2000;     // 100
    float* sedwmu = sedb1 + 100;      // 2000
    float* sedbmu = sedwmu + 2000;    // 20
    float* sedwlv = sedbmu + 20;      // 2000
    float* sedblv = sedwlv + 2000;    // 20
    float* sdzw1  = sedblv + 20;      // 2000
    float* sdzb1  = sdzw1 + 2000;     // 100
    float* wbuf   = sdzb1 + 100;      // 8 warps * 264

    {
        int t = threadIdx.x, nt = blockDim.x;
        for (int i = t; i < 10000; i += nt) sw2[i] = w2[i];
        for (int i = t; i < 2000; i += nt) { swmu[i] = wmu[i]; swlv[i] = wlv[i]; }
        for (int i = t; i < 2000; i += nt) { sedw1[i] = edw1[i]; sdzw1[i] = dzw1[i]; }
        for (int i = t; i < 2000; i += nt) { sedwmu[i] = edwmu[i]; sedwlv[i] = edwlv[i]; }
        for (int i = t; i < 100; i += nt) { sb2[i] = b2[i]; sedb1[i] = edb1[i]; sdzb1[i] = dzb1[i]; }
        if (t < 20) { sbmu[t] = bmu[t]; sblv[t] = blv[t]; sedbmu[t] = edbmu[t]; sedblv[t] = edblv[t]; }
    }
    __syncthreads();

    int wid = threadIdx.x >> 5, lane = threadIdx.x & 31;
    float* B0 = wbuf + wid * 264;
    float* B1 = B0 + 132;
    int nwarps = gridDim.x * 8;

    for (int r = blockIdx.x * 8 + wid; r < BB; r += nwarps) {
        for (int i = lane; i < HD; i += 32) B0[i] = g_h1[(size_t)r * HD + i];
        __syncwarp();

        float x[4] = {0.f, 0.f, 0.f, 0.f};
        if (lane < 25) {
            float4 bb4 = *(const float4*)&sb2[lane * 4];
            x[0] = bb4.x; x[1] = bb4.y; x[2] = bb4.z; x[3] = bb4.w;
            for (int k = 0; k < HD; k++) {
                float b = B0[k];
                float4 w = *(const float4*)&sw2[k * HD + lane * 4];
                x[0] = fmaf(b, w.x, x[0]);
                x[1] = fmaf(b, w.y, x[1]);
                x[2] = fmaf(b, w.z, x[2]);
                x[3] = fmaf(b, w.w, x[3]);
            }
        }
        float smv = x[0] + x[1] + x[2] + x[3];
        float sqv = x[0]*x[0] + x[1]*x[1] + x[2]*x[2] + x[3]*x[3];
        smv = wsum(smv); sqv = wsum(sqv);
        float mean = smv * (1.f / HD);
        float rs = rsqrtf(sqv * (1.f / HD) - mean * mean + LN_EPS);
        if (lane < 25) {
            float4 o;
            o.x = geluf((x[0] - mean) * rs);
            o.y = geluf((x[1] - mean) * rs);
            o.z = geluf((x[2] - mean) * rs);
            o.w = geluf((x[3] - mean) * rs);
            *(float4*)&B1[lane * 4] = o;
        }
        __syncwarp();

        if (lane < ZD) {
            float mu = sbmu[lane], lv = sblv[lane];
            for (int k = 0; k < HD; k++) {
                float h = B1[k];
                mu += h * swmu[k * ZD + lane];
                lv += h * swlv[k * ZD + lane];
            }
            float sc = softplus_fast(lv);
            float z = mu + sc * eps_z[(size_t)r * ZD + lane];
            o_z  [(size_t)r * ZD + lane] = z;
            o_muz[(size_t)r * ZD + lane] = mu;
            o_scz[(size_t)r * ZD + lane] = sc;
            B0[lane] = z;
        }
        __syncwarp();

        x[0] = x[1] = x[2] = x[3] = 0.f;
        if (lane < 25) {
            float4 bb4 = *(const float4*)&sedb1[lane * 4];
            x[0] = bb4.x; x[1] = bb4.y; x[2] = bb4.z; x[3] = bb4.w;
            for (int k = 0; k < ZD; k++) {
                float b = B0[k];
                float4 w = *(const float4*)&sedw1[k * HD + lane * 4];
                x[0] = fmaf(b, w.x, x[0]);
                x[1] = fmaf(b, w.y, x[1]);
                x[2] = fmaf(b, w.z, x[2]);
                x[3] = fmaf(b, w.w, x[3]);
            }
        }
        smv = x[0] + x[1] + x[2] + x[3];
        sqv = x[0]*x[0] + x[1]*x[1] + x[2]*x[2] + x[3]*x[3];
        smv = wsum(smv); sqv = wsum(sqv);
        mean = smv * (1.f / HD);
        rs = rsqrtf(sqv * (1.f / HD) - mean * mean + LN_EPS);
        if (lane < 25) {
            float4 o;
            o.x = geluf((x[0] - mean) * rs);
            o.y = geluf((x[1] - mean) * rs);
            o.z = geluf((x[2] - mean) * rs);
            o.w = geluf((x[3] - mean) * rs);
            *(float4*)&B1[lane * 4] = o;
        }
        __syncwarp();

        if (lane < ZD) {
            float mu = sedbmu[lane], lv = sedblv[lane];
            for (int k = 0; k < HD; k++) {
                float h = B1[k];
                mu += h * sedwmu[k * ZD + lane];
                lv += h * sedwlv[k * ZD + lane];
            }
            float sc = softplus_fast(lv);
            float dz = mu + sc * eps_d[(size_t)r * ZD + lane];
            o_dz [(size_t)r * ZD + lane] = dz;
            o_mud[(size_t)r * ZD + lane] = mu;
            o_scd[(size_t)r * ZD + lane] = sc;
            B0[32 + lane] = dz;
        }
        __syncwarp();

        float a[4] = {0.f,0.f,0.f,0.f}, t[4] = {0.f,0.f,0.f,0.f};
        if (lane < 25) {
            float4 bb4 = *(const float4*)&sdzb1[lane * 4];
            a[0] = bb4.x; a[1] = bb4.y; a[2] = bb4.z; a[3] = bb4.w;
            for (int k = 0; k < ZD; k++) {
                float zz = B0[k];
                float dd = B0[32 + k];
                float4 w = *(const float4*)&sdzw1[k * HD + lane * 4];
                a[0] = fmaf(zz, w.x, a[0]); t[0] = fmaf(dd, w.x, t[0]);
                a[1] = fmaf(zz, w.y, a[1]); t[1] = fmaf(dd, w.y, t[1]);
                a[2] = fmaf(zz, w.z, a[2]); t[2] = fmaf(dd, w.z, t[2]);
                a[3] = fmaf(zz, w.w, a[3]); t[3] = fmaf(dd, w.w, t[3]);
            }
        }
        float sa = a[0]+a[1]+a[2]+a[3];
        float saa = a[0]*a[0]+a[1]*a[1]+a[2]*a[2]+a[3]*a[3];
        float st = t[0]+t[1]+t[2]+t[3];
        float sat = a[0]*t[0]+a[1]*t[1]+a[2]*t[2]+a[3]*t[3];
        sa = wsum(sa); saa = wsum(saa); st = wsum(st); sat = wsum(sat);
        float m  = sa * (1.f / HD);
        float v  = saa * (1.f / HD) - m * m;
        float r2 = rsqrtf(v + LN_EPS);
        float dm = st * (1.f / HD);
        float dv = 2.f * (sat * (1.f / HD) - m * dm);
        if (lane < 25) {
            float4 oh, ot;
            float y, dy, Phi, phi;
#pragma unroll
            for (int j = 0; j < 4; j++) {
                y  = (a[j] - m) * r2;
                dy = r2 * (t[j] - dm) - 0.5f * y * r2 * r2 * dv;
                Phi = 0.5f * (1.f + erff(y * 0.70710678118654752f));
                phi = 0.3989422804014327f * expf(-0.5f * y * y);
                ((float*)&oh)[j] = y * Phi;
                ((float*)&ot)[j] = (Phi + y * phi) * dy;
            }
            *(float4*)&g_h1g[(size_t)r * HD + lane * 4] = oh;
            *(float4*)&g_th [(size_t)r * HD + lane * 4] = ot;
        }
        __syncwarp();
    }
}

// ---------------- k3: mma.sync bf16 3-split GEMM, pipelined B, fused finalize --
// Double-buffered B (register prefetch), ONE sync per chunk. 1 CTA/SM.
// smem words: A tiles 4*3840 = 15360; B 2 buffers * (hi 3840 + lo 3840).
#define RS3 60
#define TW3 (64*RS3)           // 3840 words per tile
#define OAHI 0
#define OALO (1*TW3)
#define OTHI (2*TW3)
#define OTLO (3*TW3)
#define OB(b_) (4*TW3 + (b_)*2*TW3)     // hi at +0, lo at +TW3
#define K3_SMEM_BYTES ((4*TW3 + 4*TW3) * 4)   // 122880

__global__ void __launch_bounds__(256, 1) k3_mma(
    const float* __restrict__ b2,
    float* __restrict__ o_shat, float* __restrict__ o_diff, float* __restrict__ o_pu)
{
    extern __shared__ uint32_t smu[];
    int tid = threadIdx.x, wid = tid >> 5, lane = tid & 31;
    int m0 = blockIdx.x * 64;

    // ---- stage A tiles once (zero-pad k-words 50..55) ----
    for (int lin = tid; lin < 64 * 56; lin += 256) {
        int row = lin / 56, w = lin - row * 56;
        float2 h2 = make_float2(0.f, 0.f), t2 = h2;
        if (w < 50) {
            h2 = *(const float2*)&g_h1g[(size_t)(m0 + row) * HD + 2 * w];
            t2 = *(const float2*)&g_th [(size_t)(m0 + row) * HD + 2 * w];
        }
        uint32_t hh, hl, th, tl;
        bfsplit2(h2, hh, hl);
        bfsplit2(t2, th, tl);
        int o = row * RS3 + w;
        smu[OAHI + o] = hh;
        smu[OALO + o] = hl;
        smu[OTHI + o] = th;
        smu[OTLO + o] = tl;
    }

    // B staging map: 896 uint4 items -> 4 slots/thread (slot 3 valid for tid<128)
    int bN[4], bW4[4];
#pragma unroll
    for (int i = 0; i < 4; i++) {
        int lin = tid + i * 256;
        bN [i] = lin / 14;
        bW4[i] = (lin - bN[i] * 14) * 4;
    }
    bool b3v = (tid < 128);
    uint4 bPH[4], bPL[4];

#define K3_LDG(n0_) do {                                                        \
        _Pragma("unroll")                                                       \
        for (int i_ = 0; i_ < 4; i_++) {                                        \
            if (i_ < 3 || b3v) {                                                \
                size_t src_ = (size_t)((n0_) + bN[i_]) * 56 + bW4[i_];          \
                bPH[i_] = *(const uint4*)&g_w2hi[src_];                         \
                bPL[i_] = *(const uint4*)&g_w2lo[src_];                         \
            }                                                                   \
        }                                                                       \
    } while (0)

#define K3_STS(b_) do {                                                         \
        _Pragma("unroll")                                                       \
        for (int i_ = 0; i_ < 4; i_++) {                                        \
            if (i_ < 3 || b3v) {                                                \
                *(uint4*)&smu[OB(b_) + bN[i_]*RS3 + bW4[i_]]       = bPH[i_];   \
                *(uint4*)&smu[OB(b_) + TW3 + bN[i_]*RS3 + bW4[i_]] = bPL[i_];   \
            }                                                                   \
        }                                                                       \
    } while (0)

    int g = lane >> 2, tg = lane & 3;
    int mrow = (wid & 3) * 16;
    int nbh = wid >> 2;             // 0/1
    int nb = nbh * 32;
    int arow0 = (mrow + g) * RS3;
    int arow1 = (mrow + 8 + g) * RS3;

    float sl0 = 0.f, st0 = 0.f, sl1 = 0.f, st1 = 0.f;   // fused row sums

    // prologue: stage B chunk 0
    K3_LDG(0);
    K3_STS(0);
    __syncthreads();

    int b = 0;
    for (int ch = 0; ch < 32; ch++) {
        int n0 = ch * 64;
        if (ch < 31) K3_LDG((ch + 1) * 64);

        float dH[4][4], dT[4][4];
#pragma unroll
        for (int j = 0; j < 4; j++)
#pragma unroll
            for (int e = 0; e < 4; e++) { dH[j][e] = 0.f; dT[j][e] = 0.f; }

        int obh = OB(b), obl = OB(b) + TW3;
#pragma unroll
        for (int ks = 0; ks < 7; ks++) {
            int kw = ks * 8;
            uint32_t ah0 = smu[OAHI + arow0 + kw + tg];
            uint32_t ah1 = smu[OAHI + arow1 + kw + tg];
            uint32_t ah2 = smu[OAHI + arow0 + kw + 4 + tg];
            uint32_t ah3 = smu[OAHI + arow1 + kw + 4 + tg];
            uint32_t al0 = smu[OALO + arow0 + kw + tg];
            uint32_t al1 = smu[OALO + arow1 + kw + tg];
            uint32_t al2 = smu[OALO + arow0 + kw + 4 + tg];
            uint32_t al3 = smu[OALO + arow1 + kw + 4 + tg];
            uint32_t th0 = smu[OTHI + arow0 + kw + tg];
            uint32_t th1 = smu[OTHI + arow1 + kw + tg];
            uint32_t th2 = smu[OTHI + arow0 + kw + 4 + tg];
            uint32_t th3 = smu[OTHI + arow1 + kw + 4 + tg];
            uint32_t tl0 = smu[OTLO + arow0 + kw + tg];
            uint32_t tl1 = smu[OTLO + arow1 + kw + tg];
            uint32_t tl2 = smu[OTLO + arow0 + kw + 4 + tg];
            uint32_t tl3 = smu[OTLO + arow1 + kw + 4 + tg];
            uint32_t bh0r[4], bh1r[4], bl0r[4], bl1r[4];
#pragma unroll
            for (int j = 0; j < 4; j++) {
                int brow = (nb + j * 8 + g) * RS3;
                bh0r[j] = smu[obh + brow + kw + tg];
                bh1r[j] = smu[obh + brow + kw + 4 + tg];
                bl0r[j] = smu[obl + brow + kw + tg];
                bl1r[j] = smu[obl + brow + kw + 4 + tg];
            }
#pragma unroll
            for (int j = 0; j < 4; j++)
                MMA_BF16(dH[j], ah0, ah1, ah2, ah3, bh0r[j], bh1r[j]);
#pragma unroll
            for (int j = 0; j < 4; j++)
                MMA_BF16(dT[j], th0, th1, th2, th3, bh0r[j], bh1r[j]);
#pragma unroll
            for (int j = 0; j < 4; j++)
                MMA_BF16(dH[j], ah0, ah1, ah2, ah3, bl0r[j], bl1r[j]);
#pragma unroll
            for (int j = 0; j < 4; j++)
                MMA_BF16(dT[j], th0, th1, th2, th3, bl0r[j], bl1r[j]);
#pragma unroll
            for (int j = 0; j < 4; j++)
                MMA_BF16(dH[j], al0, al1, al2, al3, bh0r[j], bh1r[j]);
#pragma unroll
            for (int j = 0; j < 4; j++)
                MMA_BF16(dT[j], tl0, tl1, tl2, tl3, bh0r[j], bh1r[j]);
        }

        // STS next chunk into the other buffer (no sync needed first)
        if (ch < 31) K3_STS(b ^ 1);

        // ---- epilogue: bias + softplus / sigmoid*tangent, store + accumulate --
        int r0 = m0 + mrow + g;
        int r1 = r0 + 8;
#pragma unroll
        for (int j = 0; j < 4; j++) {
            int c0 = n0 + nb + j * 8 + 2 * tg;
            if (c0 < XD) {
                float bx = b2[c0], by = b2[c0 + 1];
                float a0 = dH[j][0] + bx, a1 = dH[j][1] + by;
                float a2 = dH[j][2] + bx, a3 = dH[j][3] + by;
                float2 l0, t0, l1, t1;
                l0.x = softplus_fast(a0); t0.x = sigmoid_fast(a0) * dT[j][0];
                l0.y = softplus_fast(a1); t0.y = sigmoid_fast(a1) * dT[j][1];
                l1.x = softplus_fast(a2); t1.x = sigmoid_fast(a2) * dT[j][2];
                l1.y = softplus_fast(a3); t1.y = sigmoid_fast(a3) * dT[j][3];
                *(float2*)&g_ld [(size_t)r0 * XD + c0] = l0;
                *(float2*)&g_tld[(size_t)r0 * XD + c0] = t0;
                *(float2*)&g_ld [(size_t)r1 * XD + c0] = l1;
                *(float2*)&g_tld[(size_t)r1 * XD + c0] = t1;
                sl0 += l0.x + l0.y; st0 += t0.x + t0.y;
                sl1 += l1.x + l1.y; st1 += t1.x + t1.y;
            }
        }
        __syncthreads();   // B(b^1) fully written; B(b) reads done
        b ^= 1;
    }

    // ---- fused k4: per-row mean normalize + outputs ----
#pragma unroll
    for (int o = 1; o <= 2; o <<= 1) {
        sl0 += __shfl_xor_sync(0xffffffffu, sl0, o);
        st0 += __shfl_xor_sync(0xffffffffu, st0, o);
        sl1 += __shfl_xor_sync(0xffffffffu, sl1, o);
        st1 += __shfl_xor_sync(0xffffffffu, st1, o);
    }
    float* redf = (float*)smu;          // [64 rows][2 nbh][2]
    float* rowst = redf + 256;          // [64 rows][2 {rm, cm}]
    if (tg == 0) {
        int rr0 = mrow + g, rr1 = rr0 + 8;
        redf[(rr0 * 2 + nbh) * 2 + 0] = sl0;
        redf[(rr0 * 2 + nbh) * 2 + 1] = st0;
        redf[(rr1 * 2 + nbh) * 2 + 0] = sl1;
        redf[(rr1 * 2 + nbh) * 2 + 1] = st1;
    }
    __syncthreads();
    for (int r = tid; r < 64; r += 256) {
        float sl = redf[(r * 2 + 0) * 2 + 0] + redf[(r * 2 + 1) * 2 + 0];
        float st = redf[(r * 2 + 0) * 2 + 1] + redf[(r * 2 + 1) * 2 + 1];
        float m  = sl * (1.f / XD);
        float mt = st * (1.f / XD);
        rowst[r * 2 + 0] = 1.f / m;
        rowst[r * 2 + 1] = mt / (m * m);
    }
    __syncthreads();

    for (int lin = tid; lin < 64 * 500; lin += 256) {
        int row = lin / 500;
        int c = (lin - row * 500) * 4;
        float rm = rowst[row * 2 + 0];
        float cm = rowst[row * 2 + 1];
        size_t off = (size_t)(m0 + row) * XD + c;
        float4 l  = *(const float4*)&g_ld [off];
        float4 tl = *(const float4*)&g_tld[off];
        float4 be = *(const float4*)&g_beta[c];
        float4 ga = *(const float4*)&g_gamma[c];
        float4 sh, df, pu;
        sh.x = l.x * rm; df.x = 0.01f * (tl.x * rm - l.x * cm);
        sh.y = l.y * rm; df.y = 0.01f * (tl.y * rm - l.y * cm);
        sh.z = l.z * rm; df.z = 0.01f * (tl.z * rm - l.z * cm);
        sh.w = l.w * rm; df.w = 0.01f * (tl.w * rm - l.w * cm);
        pu.x = fmaxf((df.x + sh.x * ga.x) / be.x, 0.f);
        pu.y = fmaxf((df.y + sh.y * ga.y) / be.y, 0.f);
        pu.z = fmaxf((df.z + sh.z * ga.z) / be.z, 0.f);
        pu.w = fmaxf((df.w + sh.w * ga.w) / be.w, 0.f);
        *(float4*)&o_shat[off] = sh;
        *(float4*)&o_diff[off] = df;
        *(float4*)&o_pu  [off] = pu;
    }
}

// ---------------- launcher ----------------------------------------------------
extern "C" void kernel_launch(void* const* d_in, const int* in_sizes, int n_in,
                              void* d_out, int out_size)
{
    const float* s      = (const float*)d_in[0];
    const float* u      = (const float*)d_in[1];
    const float* eps_z  = (const float*)d_in[2];
    const float* eps_d  = (const float*)d_in[3];
    const float* ez_w1  = (const float*)d_in[4];
    const float* ez_b1  = (const float*)d_in[5];
    const float* ez_w2  = (const float*)d_in[6];
    const float* ez_b2  = (const float*)d_in[7];
    const float* ez_wmu = (const float*)d_in[8];
    const float* ez_bmu = (const float*)d_in[9];
    const float* ez_wlv = (const float*)d_in[10];
    const float* ez_blv = (const float*)d_in[11];
    const float* ed_w1  = (const float*)d_in[12];
    const float* ed_b1  = (const float*)d_in[13];
    const float* ed_wmu = (const float*)d_in[14];
    const float* ed_bmu = (const float*)d_in[15];
    const float* ed_wlv = (const float*)d_in[16];
    const float* ed_blv = (const float*)d_in[17];
    const float* dz_w1  = (const float*)d_in[18];
    const float* dz_b1  = (const float*)d_in[19];
    const float* dz_w2  = (const float*)d_in[20];
    const float* dz_b2  = (const float*)d_in[21];
    const float* logb   = (const float*)d_in[22];
    const float* logg   = (const float*)d_in[23];

    float* out = (float*)d_out;
    float* o_z    = out;
    float* o_dz   = o_z    + (size_t)BB * ZD;
    float* o_muz  = o_dz   + (size_t)BB * ZD;
    float* o_scz  = o_muz  + (size_t)BB * ZD;
    float* o_mud  = o_scz  + (size_t)BB * ZD;
    float* o_scd  = o_mud  + (size_t)BB * ZD;
    float* o_shat = o_scd  + (size_t)BB * ZD;
    float* o_diff = o_shat + (size_t)BB * XD;
    float* o_pu   = o_diff + (size_t)BB * XD;

    const int smem2 = K2_SMEM_FLOATS * 4;
    cudaFuncSetAttribute(k1_mma, cudaFuncAttributeMaxDynamicSharedMemorySize, K1_SMEM_BYTES);
    cudaFuncSetAttribute(k2_mid, cudaFuncAttributeMaxDynamicSharedMemorySize, smem2);
    cudaFuncSetAttribute(k3_mma, cudaFuncAttributeMaxDynamicSharedMemorySize, K3_SMEM_BYTES);

    k0_rates<<<8, 256>>>(logb, logg);
    k0b_w1split<<<(128 * 2000 + 255) / 256, 256>>>(ez_w1);
    k0c_w2split<<<(2048 * 56 + 255) / 256, 256>>>(dz_w2);
    k1_mma<<<BB / 64, 256, K1_SMEM_BYTES>>>(s, u, ez_b1);
    k2_mid<<<512, 256, smem2>>>(eps_z, eps_d,
                                ez_w2, ez_b2, ez_wmu, ez_bmu, ez_wlv, ez_blv,
                                ed_w1, ed_b1, ed_wmu, ed_bmu, ed_wlv, ed_blv,
                                dz_w1, dz_b1,
                                o_z, o_dz, o_muz, o_scz, o_mud, o_scd);
    k3_mma<<<BB / 64, 256, K3_SMEM_BYTES>>>(dz_b2, o_shat, o_diff, o_pu);
}

// round 17
// speedup vs baseline: 1.1305x; 1.1305x over previous
#include <cuda_runtime.h>
#include <cuda_bf16.h>
#include <math.h>
#include <stdint.h>

#define BB 16384
#define XD 2000
#define HD 100
#define ZD 20
#define KTOT (2*XD)      // 4000
#define LN_EPS 1e-5f

// ---------------- scratch (static device globals; no allocations) -------------
__device__ float g_h1 [(size_t)BB*HD];
__device__ float g_h1g[(size_t)BB*HD];
__device__ float g_th [(size_t)BB*HD];
__device__ float g_ld [(size_t)BB*XD];
__device__ float g_tld[(size_t)BB*XD];
__device__ float g_beta [XD];
__device__ float g_gamma[XD];
// W1 pre-transposed bf16 split: [n(128, rows >=100 zero)][kword(2000)]
__device__ uint32_t g_w1hi[128 * 2000];
__device__ uint32_t g_w1lo[128 * 2000];
// W2 pre-transposed bf16 split: [n(2048, cols >=2000 zero)][kword(56, >=50 zero)]
__device__ uint32_t g_w2hi[2048 * 56];
__device__ uint32_t g_w2lo[2048 * 56];

// ---------------- helpers -----------------------------------------------------
__device__ __forceinline__ float softplusf(float x) {
    return fmaxf(x, 0.f) + log1pf(expf(-fabsf(x)));
}
__device__ __forceinline__ float softplus_fast(float x) {
    return fmaxf(x, 0.f) + __logf(1.f + __expf(-fabsf(x)));
}
__device__ __forceinline__ float sigmoid_fast(float x) {
    return __fdividef(1.f, 1.f + __expf(-x));
}
__device__ __forceinline__ float geluf(float x) {
    return 0.5f * x * (1.f + erff(x * 0.70710678118654752f));
}
__device__ __forceinline__ float wsum(float v) {
#pragma unroll
    for (int o = 16; o; o >>= 1) v += __shfl_xor_sync(0xffffffffu, v, o);
    return v;
}

// split fp32 pair -> bf16x2 hi + bf16x2 lo (lo = rounded residual); low half = .x
__device__ __forceinline__ void bfsplit2(float2 v, uint32_t& hi, uint32_t& lo) {
    asm("cvt.rn.bf16x2.f32 %0, %1, %2;" : "=r"(hi) : "f"(v.y), "f"(v.x));
    float hx = __uint_as_float(hi << 16);
    float hy = __uint_as_float(hi & 0xFFFF0000u);
    float rx = v.x - hx;
    float ry = v.y - hy;
    asm("cvt.rn.bf16x2.f32 %0, %1, %2;" : "=r"(lo) : "f"(ry), "f"(rx));
}

// m16n8k16 bf16 MMA, fp32 accumulate (legacy HMMA path, valid at compute_103)
#define MMA_BF16(d, a0, a1, a2, a3, b0, b1) \
    asm volatile("mma.sync.aligned.m16n8k16.row.col.f32.bf16.bf16.f32 " \
        "{%0,%1,%2,%3}, {%4,%5,%6,%7}, {%8,%9}, {%0,%1,%2,%3};" \
        : "+f"((d)[0]), "+f"((d)[1]), "+f"((d)[2]), "+f"((d)[3]) \
        : "r"(a0), "r"(a1), "r"(a2), "r"(a3), "r"(b0), "r"(b1))

// ---------------- k0: beta/gamma precompute ----------------------------------
__global__ void k0_rates(const float* __restrict__ lb, const float* __restrict__ lg) {
    int i = blockIdx.x * blockDim.x + threadIdx.x;
    if (i < XD) {
        g_beta[i]  = softplusf(lb[i]);   // * DT (=1)
        g_gamma[i] = softplusf(lg[i]);
    }
}

// ---------------- k0b: W1 -> transposed bf16 split (128 rows, zero pad) -------
__global__ void k0b_w1split(const float* __restrict__ w1) {
    int idx = blockIdx.x * 256 + threadIdx.x;
    if (idx >= 128 * 2000) return;
    int n = idx / 2000, kw = idx - n * 2000;
    float2 v = make_float2(0.f, 0.f);
    if (n < HD) {
        v.x = w1[(size_t)(2 * kw) * HD + n];
        v.y = w1[(size_t)(2 * kw + 1) * HD + n];
    }
    uint32_t hi, lo;
    bfsplit2(v, hi, lo);
    g_w1hi[idx] = hi;
    g_w1lo[idx] = lo;
}

// ---------------- k0c: W2 -> transposed bf16 split (2048 x 56, zero pad) ------
__global__ void k0c_w2split(const float* __restrict__ w2) {
    int idx = blockIdx.x * 256 + threadIdx.x;
    if (idx >= 2048 * 56) return;
    int n = idx / 56, w = idx - n * 56;
    float2 v = make_float2(0.f, 0.f);
    if (n < XD && w < 50) {
        v.x = w2[(size_t)(2 * w) * XD + n];
        v.y = w2[(size_t)(2 * w + 1) * XD + n];
    }
    uint32_t hi, lo;
    bfsplit2(v, hi, lo);
    g_w2hi[idx] = hi;
    g_w2lo[idx] = lo;
}

// ---------------- k1: double-buffered mma.sync bf16-split, M64 x N112 ---------
// (unchanged — measured at the legacy-HMMA pipe ceiling, 202 us)
#define K1RS 36
#define K1BUF 12672                 // words per buffer
#define K1_AHo 0
#define K1_ALo 2304
#define K1_BHo 4608
#define K1_BLo 8640
#define K1_SMEM_BYTES (2 * K1BUF * 4)   // 101376

__global__ void __launch_bounds__(256, 1) k1_mma(
    const float* __restrict__ s, const float* __restrict__ u,
    const float* __restrict__ b1)
{
    extern __shared__ uint32_t smu[];
    int tid = threadIdx.x, wid = tid >> 5, lane = tid & 31;
    int m0 = blockIdx.x * 64;
    int g = lane >> 2, tg = lane & 3;
    int mwarp = wid & 3, nh = wid >> 2;

    int aRow[2], aW4[2];
#pragma unroll
    for (int t = 0; t < 2; t++) {
        int lin = tid + t * 256;
        aRow[t] = lin >> 3;
        aW4 [t] = (lin & 7) * 4;
    }
    int bN[4], bG4[4];
#pragma unroll
    for (int i = 0; i < 4; i++) {
        int lin = tid + i * 256;
        bN[i]  = lin >> 3;
        bG4[i] = (lin & 7) * 4;
    }
    bool b3v = (tid < 128);

    float4 aP0[2], aP1[2];
    uint4 bPH[4], bPL[4];

#define K1_LDG(kw0_) do {                                                       \
        _Pragma("unroll")                                                       \
        for (int t_ = 0; t_ < 2; t_++) {                                        \
            int kw_ = (kw0_) + aW4[t_];                                         \
            aP0[t_] = make_float4(0.f,0.f,0.f,0.f); aP1[t_] = aP0[t_];          \
            if (kw_ < 1000) {                                                   \
                const float* p_ = &s[(size_t)(m0 + aRow[t_]) * XD + 2 * kw_];   \
                aP0[t_] = *(const float4*)p_; aP1[t_] = *(const float4*)(p_+4); \
            } else if (kw_ < 2000) {                                            \
                const float* p_ = &u[(size_t)(m0 + aRow[t_]) * XD + 2*kw_ - XD];\
                aP0[t_] = *(const float4*)p_; aP1[t_] = *(const float4*)(p_+4); \
            }                                                                   \
        }                                                                       \
        _Pragma("unroll")                                                       \
        for (int i_ = 0; i_ < 4; i_++) {                                        \
            int kb_ = (kw0_) + bG4[i_];                                         \
            bPH[i_] = make_uint4(0u,0u,0u,0u); bPL[i_] = bPH[i_];               \
            if ((i_ < 3 || b3v) && kb_ < 2000) {                                \
                bPH[i_] = *(const uint4*)&g_w1hi[bN[i_] * 2000 + kb_];          \
                bPL[i_] = *(const uint4*)&g_w1lo[bN[i_] * 2000 + kb_];          \
            }                                                                   \
        }                                                                       \
    } while (0)

#define K1_STS(b_) do {                                                         \
        _Pragma("unroll")                                                       \
        for (int t_ = 0; t_ < 2; t_++) {                                        \
            uint32_t h_[4], l_[4];                                              \
            bfsplit2(make_float2(aP0[t_].x, aP0[t_].y), h_[0], l_[0]);          \
            bfsplit2(make_float2(aP0[t_].z, aP0[t_].w), h_[1], l_[1]);          \
            bfsplit2(make_float2(aP1[t_].x, aP1[t_].y), h_[2], l_[2]);          \
            bfsplit2(make_float2(aP1[t_].z, aP1[t_].w), h_[3], l_[3]);          \
            *(uint4*)&smu[(b_)*K1BUF + K1_AHo + aRow[t_]*K1RS + aW4[t_]] =      \
                make_uint4(h_[0], h_[1], h_[2], h_[3]);                         \
            *(uint4*)&smu[(b_)*K1BUF + K1_ALo + aRow[t_]*K1RS + aW4[t_]] =      \
                make_uint4(l_[0], l_[1], l_[2], l_[3]);                         \
        }                                                                       \
        _Pragma("unroll")                                                       \
        for (int i_ = 0; i_ < 4; i_++) {                                        \
            if (i_ < 3 || b3v) {                                                \
                *(uint4*)&smu[(b_)*K1BUF + K1_BHo + bN[i_]*K1RS + bG4[i_]] = bPH[i_];\
                *(uint4*)&smu[(b_)*K1BUF + K1_BLo + bN[i_]*K1RS + bG4[i_]] = bPL[i_];\
            }                                                                   \
        }                                                                       \
    } while (0)

    float dM[7][4], dL[7][4];
#pragma unroll
    for (int j = 0; j < 7; j++)
#pragma unroll
        for (int e = 0; e < 4; e++) { dM[j][e] = 0.f; dL[j][e] = 0.f; }

    K1_LDG(0);
    K1_STS(0);
    __syncthreads();

    int b = 0;
    for (int c = 0; c < 63; c++) {
        if (c < 62) K1_LDG((c + 1) * 32);

        int abH = b * K1BUF + K1_AHo + (mwarp * 16 + g) * K1RS;
        int abL = abH + (K1_ALo - K1_AHo);
#pragma unroll
        for (int ks = 0; ks < 4; ks++) {
            int kw = ks * 8 + tg;
            uint32_t ah0 = smu[abH + kw];
            uint32_t ah1 = smu[abH + 8 * K1RS + kw];
            uint32_t ah2 = smu[abH + kw + 4];
            uint32_t ah3 = smu[abH + 8 * K1RS + kw + 4];
            uint32_t al0 = smu[abL + kw];
            uint32_t al1 = smu[abL + 8 * K1RS + kw];
            uint32_t al2 = smu[abL + kw + 4];
            uint32_t al3 = smu[abL + 8 * K1RS + kw + 4];
            uint32_t bh0r[7], bh1r[7], bl0r[7], bl1r[7];
#pragma unroll
            for (int j = 0; j < 7; j++) {
                int bb = b * K1BUF + K1_BHo + (nh * 56 + 8 * j + g) * K1RS + kw;
                bh0r[j] = smu[bb];
                bh1r[j] = smu[bb + 4];
                bl0r[j] = smu[bb + (K1_BLo - K1_BHo)];
                bl1r[j] = smu[bb + (K1_BLo - K1_BHo) + 4];
            }
#pragma unroll
            for (int j = 0; j < 7; j++)
                MMA_BF16(dM[j], ah0, ah1, ah2, ah3, bh0r[j], bh1r[j]);
#pragma unroll
            for (int j = 0; j < 7; j++)
                MMA_BF16(dM[j], ah0, ah1, ah2, ah3, bl0r[j], bl1r[j]);
#pragma unroll
            for (int j = 0; j < 7; j++)
                MMA_BF16(dL[j], al0, al1, al2, al3, bh0r[j], bh1r[j]);
        }

        if (c < 62) K1_STS(b ^ 1);
        __syncthreads();
        b ^= 1;
    }

    // ---- epilogue: LN over N per row (2 halves joined via smem) + GELU ----
    float* red = (float*)smu;    // [64 rows][2 halves][2 {sum,sq}]
    int lr0 = mwarp * 16 + g;
    int lr1 = lr0 + 8;

    float s0 = 0.f, q0 = 0.f, s1 = 0.f, q1 = 0.f;
#pragma unroll
    for (int j = 0; j < 7; j++) {
        int col = nh * 56 + 8 * j + 2 * tg;
        if (col < HD) {
            float bx = b1[col], by = b1[col + 1];
            float x0 = dM[j][0] + dL[j][0] + bx;
            float x1 = dM[j][1] + dL[j][1] + by;
            float x2 = dM[j][2] + dL[j][2] + bx;
            float x3 = dM[j][3] + dL[j][3] + by;
            s0 += x0 + x1; q0 += x0 * x0 + x1 * x1;
            s1 += x2 + x3; q1 += x2 * x2 + x3 * x3;
        }
    }
#pragma unroll
    for (int o = 1; o <= 2; o <<= 1) {
        s0 += __shfl_xor_sync(0xffffffffu, s0, o);
        q0 += __shfl_xor_sync(0xffffffffu, q0, o);
        s1 += __shfl_xor_sync(0xffffffffu, s1, o);
        q1 += __shfl_xor_sync(0xffffffffu, q1, o);
    }
    if (tg == 0) {
        red[(lr0 * 2 + nh) * 2 + 0] = s0;
        red[(lr0 * 2 + nh) * 2 + 1] = q0;
        red[(lr1 * 2 + nh) * 2 + 0] = s1;
        red[(lr1 * 2 + nh) * 2 + 1] = q1;
    }
    __syncthreads();

    float sum0 = red[(lr0*2+0)*2] + red[(lr0*2+1)*2];
    float sq0  = red[(lr0*2+0)*2+1] + red[(lr0*2+1)*2+1];
    float sum1 = red[(lr1*2+0)*2] + red[(lr1*2+1)*2];
    float sq1  = red[(lr1*2+0)*2+1] + red[(lr1*2+1)*2+1];
    float mean0 = sum0 * (1.f / HD);
    float mean1 = sum1 * (1.f / HD);
    float rs0 = rsqrtf(sq0 * (1.f / HD) - mean0 * mean0 + LN_EPS);
    float rs1 = rsqrtf(sq1 * (1.f / HD) - mean1 * mean1 + LN_EPS);

    int r0 = m0 + lr0, r1 = m0 + lr1;
#pragma unroll
    for (int j = 0; j < 7; j++) {
        int col = nh * 56 + 8 * j + 2 * tg;
        if (col < HD) {
            float bx = b1[col], by = b1[col + 1];
            float2 o0, o1;
            o0.x = geluf((dM[j][0] + dL[j][0] + bx - mean0) * rs0);
            o0.y = geluf((dM[j][1] + dL[j][1] + by - mean0) * rs0);
            o1.x = geluf((dM[j][2] + dL[j][2] + bx - mean1) * rs1);
            o1.y = geluf((dM[j][3] + dL[j][3] + by - mean1) * rs1);
            *(float2*)&g_h1[(size_t)r0 * HD + col] = o0;
            *(float2*)&g_h1[(size_t)r1 * HD + col] = o1;
        }
    }
}

// ---------------- k2: everything small, one warp per row (smem w2) ------------
#define K2_SMEM_FLOATS (22380 + 8*264)
__global__ void __launch_bounds__(256) k2_mid(
    const float* __restrict__ eps_z, const float* __restrict__ eps_d,
    const float* __restrict__ w2, const float* __restrict__ b2,
    const float* __restrict__ wmu, const float* __restrict__ bmu,
    const float* __restrict__ wlv, const float* __restrict__ blv,
    const float* __restrict__ edw1, const float* __restrict__ edb1,
    const float* __restrict__ edwmu, const float* __restrict__ edbmu,
    const float* __restrict__ edwlv, const float* __restrict__ edblv,
    const float* __restrict__ dzw1, const float* __restrict__ dzb1,
    float* __restrict__ o_z, float* __restrict__ o_dz,
    float* __restrict__ o_muz, float* __restrict__ o_scz,
    float* __restrict__ o_mud, float* __restrict__ o_scd)
{
    extern __shared__ float sm2[];
    float* sw2    = sm2;              // 10000
    float* swmu   = sw2 + 10000;      // 2000
    float* swlv   = swmu + 2000;      // 2000
    float* sb2    = swlv + 2000;      // 100
    float* sbmu   = sb2 + 100;        // 20
    float* sblv   = sbmu + 20;        // 20
    float* sedw1  = sblv + 20;        // 2000
    float* sedb1  = sedw1 + 2000;     // 100
    float* sedwmu = sedb1 + 100;      // 2000
    float* sedbmu = sedwmu + 2000;    // 20
    float* sedwlv = sedbmu + 20;      // 2000
    float* sedblv = sedwlv + 2000;    // 20
    float* sdzw1  = sedblv + 20;      // 2000
    float* sdzb1  = sdzw1 + 2000;     // 100
    float* wbuf   = sdzb1 + 100;      // 8 warps * 264

    {
        int t = threadIdx.x, nt = blockDim.x;
        for (int i = t; i < 10000; i += nt) sw2[i] = w2[i];
        for (int i = t; i < 2000; i += nt) { swmu[i] = wmu[i]; swlv[i] = wlv[i]; }
        for (int i = t; i < 2000; i += nt) { sedw1[i] = edw1[i]; sdzw1[i] = dzw1[i]; }
        for (int i = t; i < 2000; i += nt) { sedwmu[i] = edwmu[i]; sedwlv[i] = edwlv[i]; }
        for (int i = t; i < 100; i += nt) { sb2[i] = b2[i]; sedb1[i] = edb1[i]; sdzb1[i] = dzb1[i]; }
        if (t < 20) { sbmu[t] = bmu[t]; sblv[t] = blv[t]; sedbmu[t] = edbmu[t]; sedblv[t] = edblv[t]; }
    }
    __syncthreads();

    int wid = threadIdx.x >> 5, lane = threadIdx.x & 31;
    float* B0 = wbuf + wid * 264;
    float* B1 = B0 + 132;
    int nwarps = gridDim.x * 8;

    for (int r = blockIdx.x * 8 + wid; r < BB; r += nwarps) {
        for (int i = lane; i < HD; i += 32) B0[i] = g_h1[(size_t)r * HD + i];
        __syncwarp();

        float x[4] = {0.f, 0.f, 0.f, 0.f};
        if (lane < 25) {
            float4 bb4 = *(const float4*)&sb2[lane * 4];
            x[0] = bb4.x; x[1] = bb4.y; x[2] = bb4.z; x[3] = bb4.w;
            for (int k = 0; k < HD; k++) {
                float b = B0[k];
                float4 w = *(const float4*)&sw2[k * HD + lane * 4];
                x[0] = fmaf(b, w.x, x[0]);
                x[1] = fmaf(b, w.y, x[1]);
                x[2] = fmaf(b, w.z, x[2]);
                x[3] = fmaf(b, w.w, x[3]);
            }
        }
        float smv = x[0] + x[1] + x[2] + x[3];
        float sqv = x[0]*x[0] + x[1]*x[1] + x[2]*x[2] + x[3]*x[3];
        smv = wsum(smv); sqv = wsum(sqv);
        float mean = smv * (1.f / HD);
        float rs = rsqrtf(sqv * (1.f / HD) - mean * mean + LN_EPS);
        if (lane < 25) {
            float4 o;
            o.x = geluf((x[0] - mean) * rs);
            o.y = geluf((x[1] - mean) * rs);
            o.z = geluf((x[2] - mean) * rs);
            o.w = geluf((x[3] - mean) * rs);
            *(float4*)&B1[lane * 4] = o;
        }
        __syncwarp();

        if (lane < ZD) {
            float mu = sbmu[lane], lv = sblv[lane];
            for (int k = 0; k < HD; k++) {
                float h = B1[k];
                mu += h * swmu[k * ZD + lane];
                lv += h * swlv[k * ZD + lane];
            }
            float sc = softplus_fast(lv);
            float z = mu + sc * eps_z[(size_t)r * ZD + lane];
            o_z  [(size_t)r * ZD + lane] = z;
            o_muz[(size_t)r * ZD + lane] = mu;
            o_scz[(size_t)r * ZD + lane] = sc;
            B0[lane] = z;
        }
        __syncwarp();

        x[0] = x[1] = x[2] = x[3] = 0.f;
        if (lane < 25) {
            float4 bb4 = *(const float4*)&sedb1[lane * 4];
            x[0] = bb4.x; x[1] = bb4.y; x[2] = bb4.z; x[3] = bb4.w;
            for (int k = 0; k < ZD; k++) {
                float b = B0[k];
                float4 w = *(const float4*)&sedw1[k * HD + lane * 4];
                x[0] = fmaf(b, w.x, x[0]);
                x[1] = fmaf(b, w.y, x[1]);
                x[2] = fmaf(b, w.z, x[2]);
                x[3] = fmaf(b, w.w, x[3]);
            }
        }
        smv = x[0] + x[1] + x[2] + x[3];
        sqv = x[0]*x[0] + x[1]*x[1] + x[2]*x[2] + x[3]*x[3];
        smv = wsum(smv); sqv = wsum(sqv);
        mean = smv * (1.f / HD);
        rs = rsqrtf(sqv * (1.f / HD) - mean * mean + LN_EPS);
        if (lane < 25) {
            float4 o;
            o.x = geluf((x[0] - mean) * rs);
            o.y = geluf((x[1] - mean) * rs);
            o.z = geluf((x[2] - mean) * rs);
            o.w = geluf((x[3] - mean) * rs);
            *(float4*)&B1[lane * 4] = o;
        }
        __syncwarp();

        if (lane < ZD) {
            float mu = sedbmu[lane], lv = sedblv[lane];
            for (int k = 0; k < HD; k++) {
                float h = B1[k];
                mu += h * sedwmu[k * ZD + lane];
                lv += h * sedwlv[k * ZD + lane];
            }
            float sc = softplus_fast(lv);
            float dz = mu + sc * eps_d[(size_t)r * ZD + lane];
            o_dz [(size_t)r * ZD + lane] = dz;
            o_mud[(size_t)r * ZD + lane] = mu;
            o_scd[(size_t)r * ZD + lane] = sc;
            B0[32 + lane] = dz;
        }
        __syncwarp();

        float a[4] = {0.f,0.f,0.f,0.f}, t[4] = {0.f,0.f,0.f,0.f};
        if (lane < 25) {
            float4 bb4 = *(const float4*)&sdzb1[lane * 4];
            a[0] = bb4.x; a[1] = bb4.y; a[2] = bb4.z; a[3] = bb4.w;
            for (int k = 0; k < ZD; k++) {
                float zz = B0[k];
                float dd = B0[32 + k];
                float4 w = *(const float4*)&sdzw1[k * HD + lane * 4];
                a[0] = fmaf(zz, w.x, a[0]); t[0] = fmaf(dd, w.x, t[0]);
                a[1] = fmaf(zz, w.y, a[1]); t[1] = fmaf(dd, w.y, t[1]);
                a[2] = fmaf(zz, w.z, a[2]); t[2] = fmaf(dd, w.z, t[2]);
                a[3] = fmaf(zz, w.w, a[3]); t[3] = fmaf(dd, w.w, t[3]);
            }
        }
        float sa = a[0]+a[1]+a[2]+a[3];
        float saa = a[0]*a[0]+a[1]*a[1]+a[2]*a[2]+a[3]*a[3];
        float st = t[0]+t[1]+t[2]+t[3];
        float sat = a[0]*t[0]+a[1]*t[1]+a[2]*t[2]+a[3]*t[3];
        sa = wsum(sa); saa = wsum(saa); st = wsum(st); sat = wsum(sat);
        float m  = sa * (1.f / HD);
        float v  = saa * (1.f / HD) - m * m;
        float r2 = rsqrtf(v + LN_EPS);
        float dm = st * (1.f / HD);
        float dv = 2.f * (sat * (1.f / HD) - m * dm);
        if (lane < 25) {
            float4 oh, ot;
            float y, dy, Phi, phi;
#pragma unroll
            for (int j = 0; j < 4; j++) {
                y  = (a[j] - m) * r2;
                dy = r2 * (t[j] - dm) - 0.5f * y * r2 * r2 * dv;
                Phi = 0.5f * (1.f + erff(y * 0.70710678118654752f));
                phi = 0.3989422804014327f * expf(-0.5f * y * y);
                ((float*)&oh)[j] = y * Phi;
                ((float*)&ot)[j] = (Phi + y * phi) * dy;
            }
            *(float4*)&g_h1g[(size_t)r * HD + lane * 4] = oh;
            *(float4*)&g_th [(size_t)r * HD + lane * 4] = ot;
        }
        __syncwarp();
    }
}

// ---------------- k3: mma.sync bf16 3-split GEMM + fused finalize --------------
// Single B buffer (92KB, 2 CTAs/SM = ONE wave), register prefetch of next
// chunk's B before the MMA loop; STS after read-fence sync; epilogue overlaps
// the STS drain before the second sync.
#define RS3 60
#define TW3 (64*RS3)           // words per tile = 3840
#define OAHI 0
#define OALO (1*TW3)
#define OTHI (2*TW3)
#define OTLO (3*TW3)
#define OBHI (4*TW3)
#define OBLO (5*TW3)
#define K3_SMEM_BYTES (6*TW3*4)   // 92160

__global__ void __launch_bounds__(256, 2) k3_mma(
    const float* __restrict__ b2,
    float* __restrict__ o_shat, float* __restrict__ o_diff, float* __restrict__ o_pu)
{
    extern __shared__ uint32_t smu[];
    int tid = threadIdx.x, wid = tid >> 5, lane = tid & 31;
    int m0 = blockIdx.x * 64;

    // ---- stage A tiles once (zero-pad k-words 50..55) ----
    for (int lin = tid; lin < 64 * 56; lin += 256) {
        int row = lin / 56, w = lin - row * 56;
        float2 h2 = make_float2(0.f, 0.f), t2 = h2;
        if (w < 50) {
            h2 = *(const float2*)&g_h1g[(size_t)(m0 + row) * HD + 2 * w];
            t2 = *(const float2*)&g_th [(size_t)(m0 + row) * HD + 2 * w];
        }
        uint32_t hh, hl, th, tl;
        bfsplit2(h2, hh, hl);
        bfsplit2(t2, th, tl);
        int o = row * RS3 + w;
        smu[OAHI + o] = hh;
        smu[OALO + o] = hl;
        smu[OTHI + o] = th;
        smu[OTLO + o] = tl;
    }

    // B staging map: 896 uint4 items -> 4 slots/thread (slot 3 valid for tid<128)
    int bN[4], bW4[4];
#pragma unroll
    for (int i = 0; i < 4; i++) {
        int lin = tid + i * 256;
        bN [i] = lin / 14;
        bW4[i] = (lin - bN[i] * 14) * 4;
    }
    bool b3v = (tid < 128);
    uint4 bPH[4], bPL[4];

#define K3_LDG(n0_) do {                                                        \
        _Pragma("unroll")                                                       \
        for (int i_ = 0; i_ < 4; i_++) {                                        \
            if (i_ < 3 || b3v) {                                                \
                size_t src_ = (size_t)((n0_) + bN[i_]) * 56 + bW4[i_];          \
                bPH[i_] = *(const uint4*)&g_w2hi[src_];                         \
                bPL[i_] = *(const uint4*)&g_w2lo[src_];                         \
            }                                                                   \
        }                                                                       \
    } while (0)

#define K3_STS() do {                                                           \
        _Pragma("unroll")                                                       \
        for (int i_ = 0; i_ < 4; i_++) {                                        \
            if (i_ < 3 || b3v) {                                                \
                *(uint4*)&smu[OBHI + bN[i_]*RS3 + bW4[i_]] = bPH[i_];           \
                *(uint4*)&smu[OBLO + bN[i_]*RS3 + bW4[i_]] = bPL[i_];           \
            }                                                                   \
        }                                                                       \
    } while (0)

    int g = lane >> 2, tg = lane & 3;
    int mrow = (wid & 3) * 16;
    int nbh = wid >> 2;             // 0/1
    int nb = nbh * 32;
    int arow0 = (mrow + g) * RS3;
    int arow1 = (mrow + 8 + g) * RS3;

    float sl0 = 0.f, st0 = 0.f, sl1 = 0.f, st1 = 0.f;   // fused row sums

    // prologue: stage B chunk 0
    K3_LDG(0);
    K3_STS();
    __syncthreads();

    for (int ch = 0; ch < 32; ch++) {
        int n0 = ch * 64;
        if (ch < 31) K3_LDG((ch + 1) * 64);   // regs, hidden under MMA

        float dH[4][4], dT[4][4];
#pragma unroll
        for (int j = 0; j < 4; j++)
#pragma unroll
            for (int e = 0; e < 4; e++) { dH[j][e] = 0.f; dT[j][e] = 0.f; }

#pragma unroll
        for (int ks = 0; ks < 7; ks++) {
            int kw = ks * 8;
            uint32_t ah0 = smu[OAHI + arow0 + kw + tg];
            uint32_t ah1 = smu[OAHI + arow1 + kw + tg];
            uint32_t ah2 = smu[OAHI + arow0 + kw + 4 + tg];
            uint32_t ah3 = smu[OAHI + arow1 + kw + 4 + tg];
            uint32_t al0 = smu[OALO + arow0 + kw + tg];
            uint32_t al1 = smu[OALO + arow1 + kw + tg];
            uint32_t al2 = smu[OALO + arow0 + kw + 4 + tg];
            uint32_t al3 = smu[OALO + arow1 + kw + 4 + tg];
            uint32_t th0 = smu[OTHI + arow0 + kw + tg];
            uint32_t th1 = smu[OTHI + arow1 + kw + tg];
            uint32_t th2 = smu[OTHI + arow0 + kw + 4 + tg];
            uint32_t th3 = smu[OTHI + arow1 + kw + 4 + tg];
            uint32_t tl0 = smu[OTLO + arow0 + kw + tg];
            uint32_t tl1 = smu[OTLO + arow1 + kw + tg];
            uint32_t tl2 = smu[OTLO + arow0 + kw + 4 + tg];
            uint32_t tl3 = smu[OTLO + arow1 + kw + 4 + tg];
            uint32_t bh0r[4], bh1r[4], bl0r[4], bl1r[4];
#pragma unroll
            for (int j = 0; j < 4; j++) {
                int brow = (nb + j * 8 + g) * RS3;
                bh0r[j] = smu[OBHI + brow + kw + tg];
                bh1r[j] = smu[OBHI + brow + kw + 4 + tg];
                bl0r[j] = smu[OBLO + brow + kw + tg];
                bl1r[j] = smu[OBLO + brow + kw + 4 + tg];
            }
#pragma unroll
            for (int j = 0; j < 4; j++)
                MMA_BF16(dH[j], ah0, ah1, ah2, ah3, bh0r[j], bh1r[j]);
#pragma unroll
            for (int j = 0; j < 4; j++)
                MMA_BF16(dT[j], th0, th1, th2, th3, bh0r[j], bh1r[j]);
#pragma unroll
            for (int j = 0; j < 4; j++)
                MMA_BF16(dH[j], ah0, ah1, ah2, ah3, bl0r[j], bl1r[j]);
#pragma unroll
            for (int j = 0; j < 4; j++)
                MMA_BF16(dT[j], th0, th1, th2, th3, bl0r[j], bl1r[j]);
#pragma unroll
            for (int j = 0; j < 4; j++)
                MMA_BF16(dH[j], al0, al1, al2, al3, bh0r[j], bh1r[j]);
#pragma unroll
            for (int j = 0; j < 4; j++)
                MMA_BF16(dT[j], tl0, tl1, tl2, tl3, bh0r[j], bh1r[j]);
        }
        __syncthreads();   // all B reads done before overwrite

        if (ch < 31) K3_STS();   // write next chunk (overlaps epilogue below)

        // ---- epilogue: bias + softplus / sigmoid*tangent, store + accumulate --
        int r0 = m0 + mrow + g;
        int r1 = r0 + 8;
#pragma unroll
        for (int j = 0; j < 4; j++) {
            int c0 = n0 + nb + j * 8 + 2 * tg;
            if (c0 < XD) {
                float bx = b2[c0], by = b2[c0 + 1];
                float a0 = dH[j][0] + bx, a1 = dH[j][1] + by;
                float a2 = dH[j][2] + bx, a3 = dH[j][3] + by;
                float2 l0, t0, l1, t1;
                l0.x = softplus_fast(a0); t0.x = sigmoid_fast(a0) * dT[j][0];
                l0.y = softplus_fast(a1); t0.y = sigmoid_fast(a1) * dT[j][1];
                l1.x = softplus_fast(a2); t1.x = sigmoid_fast(a2) * dT[j][2];
                l1.y = softplus_fast(a3); t1.y = sigmoid_fast(a3) * dT[j][3];
                *(float2*)&g_ld [(size_t)r0 * XD + c0] = l0;
                *(float2*)&g_tld[(size_t)r0 * XD + c0] = t0;
                *(float2*)&g_ld [(size_t)r1 * XD + c0] = l1;
                *(float2*)&g_tld[(size_t)r1 * XD + c0] = t1;
                sl0 += l0.x + l0.y; st0 += t0.x + t0.y;
                sl1 += l1.x + l1.y; st1 += t1.x + t1.y;
            }
        }
        __syncthreads();   // STS visible before next chunk's MMA reads
    }

    // ---- fused k4: per-row mean normalize + outputs ----
#pragma unroll
    for (int o = 1; o <= 2; o <<= 1) {
        sl0 += __shfl_xor_sync(0xffffffffu, sl0, o);
        st0 += __shfl_xor_sync(0xffffffffu, st0, o);
        sl1 += __shfl_xor_sync(0xffffffffu, sl1, o);
        st1 += __shfl_xor_sync(0xffffffffu, st1, o);
    }
    float* redf = (float*)smu;          // [64 rows][2 nbh][2]
    float* rowst = redf + 256;          // [64 rows][2 {rm, cm}]
    if (tg == 0) {
        int rr0 = mrow + g, rr1 = rr0 + 8;
        redf[(rr0 * 2 + nbh) * 2 + 0] = sl0;
        redf[(rr0 * 2 + nbh) * 2 + 1] = st0;
        redf[(rr1 * 2 + nbh) * 2 + 0] = sl1;
        redf[(rr1 * 2 + nbh) * 2 + 1] = st1;
    }
    __syncthreads();
    for (int r = tid; r < 64; r += 256) {
        float sl = redf[(r * 2 + 0) * 2 + 0] + redf[(r * 2 + 1) * 2 + 0];
        float st = redf[(r * 2 + 0) * 2 + 1] + redf[(r * 2 + 1) * 2 + 1];
        float m  = sl * (1.f / XD);
        float mt = st * (1.f / XD);
        rowst[r * 2 + 0] = 1.f / m;
        rowst[r * 2 + 1] = mt / (m * m);
    }
    __syncthreads();

    for (int lin = tid; lin < 64 * 500; lin += 256) {
        int row = lin / 500;
        int c = (lin - row * 500) * 4;
        float rm = rowst[row * 2 + 0];
        float cm = rowst[row * 2 + 1];
        size_t off = (size_t)(m0 + row) * XD + c;
        float4 l  = *(const float4*)&g_ld [off];
        float4 tl = *(const float4*)&g_tld[off];
        float4 be = *(const float4*)&g_beta[c];
        float4 ga = *(const float4*)&g_gamma[c];
        float4 sh, df, pu;
        sh.x = l.x * rm; df.x = 0.01f * (tl.x * rm - l.x * cm);
        sh.y = l.y * rm; df.y = 0.01f * (tl.y * rm - l.y * cm);
        sh.z = l.z * rm; df.z = 0.01f * (tl.z * rm - l.z * cm);
        sh.w = l.w * rm; df.w = 0.01f * (tl.w * rm - l.w * cm);
        pu.x = fmaxf((df.x + sh.x * ga.x) / be.x, 0.f);
        pu.y = fmaxf((df.y + sh.y * ga.y) / be.y, 0.f);
        pu.z = fmaxf((df.z + sh.z * ga.z) / be.z, 0.f);
        pu.w = fmaxf((df.w + sh.w * ga.w) / be.w, 0.f);
        *(float4*)&o_shat[off] = sh;
        *(float4*)&o_diff[off] = df;
        *(float4*)&o_pu  [off] = pu;
    }
}

// ---------------- launcher ----------------------------------------------------
extern "C" void kernel_launch(void* const* d_in, const int* in_sizes, int n_in,
                              void* d_out, int out_size)
{
    const float* s      = (const float*)d_in[0];
    const float* u      = (const float*)d_in[1];
    const float* eps_z  = (const float*)d_in[2];
    const float* eps_d  = (const float*)d_in[3];
    const float* ez_w1  = (const float*)d_in[4];
    const float* ez_b1  = (const float*)d_in[5];
    const float* ez_w2  = (const float*)d_in[6];
    const float* ez_b2  = (const float*)d_in[7];
    const float* ez_wmu = (const float*)d_in[8];
    const float* ez_bmu = (const float*)d_in[9];
    const float* ez_wlv = (const float*)d_in[10];
    const float* ez_blv = (const float*)d_in[11];
    const float* ed_w1  = (const float*)d_in[12];
    const float* ed_b1  = (const float*)d_in[13];
    const float* ed_wmu = (const float*)d_in[14];
    const float* ed_bmu = (const float*)d_in[15];
    const float* ed_wlv = (const float*)d_in[16];
    const float* ed_blv = (const float*)d_in[17];
    const float* dz_w1  = (const float*)d_in[18];
    const float* dz_b1  = (const float*)d_in[19];
    const float* dz_w2  = (const float*)d_in[20];
    const float* dz_b2  = (const float*)d_in[21];
    const float* logb   = (const float*)d_in[22];
    const float* logg   = (const float*)d_in[23];

    float* out = (float*)d_out;
    float* o_z    = out;
    float* o_dz   = o_z    + (size_t)BB * ZD;
    float* o_muz  = o_dz   + (size_t)BB * ZD;
    float* o_scz  = o_muz  + (size_t)BB * ZD;
    float* o_mud  = o_scz  + (size_t)BB * ZD;
    float* o_scd  = o_mud  + (size_t)BB * ZD;
    float* o_shat = o_scd  + (size_t)BB * ZD;
    float* o_diff = o_shat + (size_t)BB * XD;
    float* o_pu   = o_diff + (size_t)BB * XD;

    const int smem2 = K2_SMEM_FLOATS * 4;
    cudaFuncSetAttribute(k1_mma, cudaFuncAttributeMaxDynamicSharedMemorySize, K1_SMEM_BYTES);
    cudaFuncSetAttribute(k2_mid, cudaFuncAttributeMaxDynamicSharedMemorySize, smem2);
    cudaFuncSetAttribute(k3_mma, cudaFuncAttributeMaxDynamicSharedMemorySize, K3_SMEM_BYTES);

    k0_rates<<<8, 256>>>(logb, logg);
    k0b_w1split<<<(128 * 2000 + 255) / 256, 256>>>(ez_w1);
    k0c_w2split<<<(2048 * 56 + 255) / 256, 256>>>(dz_w2);
    k1_mma<<<BB / 64, 256, K1_SMEM_BYTES>>>(s, u, ez_b1);
    k2_mid<<<512, 256, smem2>>>(eps_z, eps_d,
                                ez_w2, ez_b2, ez_wmu, ez_bmu, ez_wlv, ez_blv,
                                ed_w1, ed_b1, ed_wmu, ed_bmu, ed_wlv, ed_blv,
                                dz_w1, dz_b1,
                                o_z, o_dz, o_muz, o_scz, o_mud, o_scd);
    k3_mma<<<BB / 64, 256, K3_SMEM_BYTES>>>(dz_b2, o_shat, o_diff, o_pu);
}